// round 9
// baseline (speedup 1.0000x reference)
#include <cuda_runtime.h>

#define DPRED    84
#define NCLS     80
#define MAXB     8
#define MAXA     76725
#define NBINS    4096
#define KMAX     512
#define KTARGET  128
#define PER_LANE (KMAX / 32)
#define MAXDET   100
#define CONF_T   0.05f
#define IOU_T    0.5f
#define NMS_NT   256

typedef unsigned long long u64;

// ---------------- device scratch (no allocation allowed) ----------------
__device__ float4 g_boxes8[MAXB * MAXA * 2];  // cx,cy,w,h | cls,conf,0,0
__device__ float  g_scores[MAXB * MAXA];      // conf if >= CONF_T else 0
__device__ int    g_hist[MAXB * NBINS];       // zero-init; re-zeroed by thresh
__device__ float  g_thresh[MAXB];
__device__ int    g_cnt[MAXB];
__device__ int    g_cand[MAXB * KMAX];

// ---------------- decode: thread per anchor (best measured config) -------
__global__ void __launch_bounds__(256)
decode_kernel(const float* __restrict__ pred,
              const float* __restrict__ anchors,
              int B, int A) {
    int i = blockIdx.x * blockDim.x + threadIdx.x;
    if (i >= B * A) return;

    const float4* row = reinterpret_cast<const float4*>(pred + (size_t)i * DPRED);

    float4 v0 = __ldg(row + 0);                 // box preds

    // branchless first-occurrence argmax over 80 class logits
    float best = -3.4e38f;
    int   cls  = 0;
#pragma unroll
    for (int j = 1; j <= 20; j++) {
        float4 c = __ldg(row + j);
        int base = (j - 1) * 4;
        if (c.x > best) { best = c.x; cls = base + 0; }
        if (c.y > best) { best = c.y; cls = base + 1; }
        if (c.z > best) { best = c.z; cls = base + 2; }
        if (c.w > best) { best = c.w; cls = base + 3; }
    }

    int b = i / A;
    int a = i - b * A;

    float4 an = __ldg(reinterpret_cast<const float4*>(anchors) + a);
    float cx = v0.x * 0.1f * an.z + an.x;
    float cy = v0.y * 0.1f * an.w + an.y;
    float w  = expf(v0.z * 0.2f) * an.z;
    float h  = expf(v0.w * 0.2f) * an.w;
    float conf = 1.0f / (1.0f + expf(-best));

    g_boxes8[(size_t)i * 2 + 0] = make_float4(cx, cy, w, h);
    g_boxes8[(size_t)i * 2 + 1] = make_float4((float)cls, conf, 0.f, 0.f);

    float s = (conf >= CONF_T) ? conf : 0.0f;
    g_scores[i] = s;
    if (s > 0.0f) {
        int bin = (int)(s * (float)NBINS);
        if (bin > NBINS - 1) bin = NBINS - 1;
        if (bin < 1) bin = 1;
        atomicAdd(&g_hist[b * NBINS + bin], 1);
    }
}

// ------- threshold from histogram (and re-zero hist for next call) -------
__global__ void __launch_bounds__(512)
thresh_kernel() {
    int b   = blockIdx.x;
    int tid = threadIdx.x;
    __shared__ int sh[NBINS];
    __shared__ int csum[128];          // 32-bin chunk sums

    for (int i = tid; i < NBINS; i += 512)
        sh[i] = g_hist[b * NBINS + i];
    __syncthreads();

    // re-zero for the next graph replay (deterministic pipeline state)
    for (int i = tid; i < NBINS; i += 512)
        g_hist[b * NBINS + i] = 0;

    if (tid < 128) {
        int s = 0, base = tid * 32;
#pragma unroll
        for (int j = 0; j < 32; j++) s += sh[base + j];
        csum[tid] = s;
    }
    __syncthreads();

    if (tid == 0) {
        int cum = 0, binSel = NBINS, c = 128;
        while (c > 1 && cum < KTARGET && cum + csum[c - 1] <= KMAX) {
            c--; cum += csum[c]; binSel = c * 32;
        }
        if (cum < KTARGET && c >= 1) {
            for (int bin = c * 32 - 1; bin >= (c - 1) * 32 && bin >= 1; --bin) {
                int h = sh[bin];
                if (cum + h > KMAX) break;
                cum += h; binSel = bin;
                if (cum >= KTARGET) break;
            }
        }
        g_thresh[b] = (float)binSel / (float)NBINS;
        g_cnt[b]    = 0;
    }
}

// ---------------- compact candidates: many blocks per batch --------------
__global__ void compact_kernel(int A) {
    int b = blockIdx.y;
    float th = g_thresh[b];
    const float* sc = g_scores + (size_t)b * A;
    for (int i = blockIdx.x * blockDim.x + threadIdx.x; i < A;
         i += gridDim.x * blockDim.x) {
        if (sc[i] > th) {
            int p = atomicAdd(&g_cnt[b], 1);
            if (p < KMAX) g_cand[b * KMAX + p] = i;
        }
    }
}

// ------- NMS: block per batch, warp-0 register-resident, unrolled --------
__global__ void __launch_bounds__(NMS_NT, 1)
nms_kernel(float* __restrict__ out, int A) {
    int b   = blockIdx.x;
    int tid = threadIdx.x;

    __shared__ u64   skey[KMAX];
    __shared__ float sx1[KMAX], sy1[KMAX], sx2[KMAX], sy2[KMAX], sar[KMAX];
    __shared__ float scx[KMAX], scy[KMAX], swd[KMAX], sht[KMAX];
    __shared__ int   scls[KMAX];
    __shared__ int   sFallback;
    __shared__ u64   sBest;
    __shared__ u64   redk[NMS_NT / 32];

    int cnt = g_cnt[b];
    bool overflow = (cnt > KMAX);
    if (cnt > KMAX) cnt = KMAX;

    for (int i = tid; i < cnt; i += NMS_NT) {
        int a = g_cand[b * KMAX + i];
        size_t base = ((size_t)b * A + a) * 2;
        float4 p0 = g_boxes8[base + 0];
        float4 p1 = g_boxes8[base + 1];
        float hw = 0.5f * p0.z, hh = 0.5f * p0.w;
        sx1[i] = p0.x - hw; sy1[i] = p0.y - hh;
        sx2[i] = p0.x + hw; sy2[i] = p0.y + hh;
        sar[i] = p0.z * p0.w;
        scx[i] = p0.x; scy[i] = p0.y; swd[i] = p0.z; sht[i] = p0.w;
        scls[i] = (int)p1.x;
        skey[i] = ((u64)__float_as_uint(p1.y) << 32) |
                  (unsigned)(0x7FFFFFFF - a);
    }
    if (tid == 0) sFallback = overflow ? 1 : 0;
    __syncthreads();

    // ---- fast path: warp 0, candidates in registers, branchless loops ----
    if (tid < 32 && !sFallback) {
        int lane = tid;
        u64   kk[PER_LANE];
        float rx1[PER_LANE], ry1[PER_LANE], rx2[PER_LANE], ry2[PER_LANE];
        float rar[PER_LANE];
        int   rcl[PER_LANE];
#pragma unroll
        for (int t = 0; t < PER_LANE; t++) {
            int i = t * 32 + lane;
            bool ok = (i < cnt);
            kk[t]  = ok ? skey[i] : 0ull;
            rx1[t] = ok ? sx1[i] : 0.f;
            ry1[t] = ok ? sy1[i] : 0.f;
            rx2[t] = ok ? sx2[i] : 0.f;
            ry2[t] = ok ? sy2[i] : 0.f;
            rar[t] = ok ? sar[i] : 0.f;
            rcl[t] = ok ? scls[i] : -1;
        }

        for (int d = 0; d < MAXDET; d++) {
            // lane-local max key, statically unrolled (no LDS, no branches)
            u64 bk = kk[0]; int bs = 0;
#pragma unroll
            for (int t = 1; t < PER_LANE; t++)
                if (kk[t] > bk) { bk = kk[t]; bs = t; }

            unsigned hi  = (unsigned)(bk >> 32);
            unsigned mhi = __reduce_max_sync(0xffffffffu, hi);
            if (mhi == 0u) {                 // pool exhausted -> exact path
                if (lane == 0) sFallback = 1;
                break;
            }
            unsigned lo  = (hi == mhi) ? (unsigned)bk : 0u;
            unsigned mlo = __reduce_max_sync(0xffffffffu, lo);
            u64 selKey = ((u64)mhi << 32) | mlo;

            bool win = (bk == selKey);       // keys unique -> one winner
            unsigned wm = __ballot_sync(0xffffffffu, win);
            int wl   = __ffs(wm) - 1;
            int slot = __shfl_sync(0xffffffffu, bs, wl) * 32 + wl;

            float X1 = sx1[slot], Y1 = sy1[slot];    // broadcast LDS
            float X2 = sx2[slot], Y2 = sy2[slot];
            float AR = sar[slot];
            int   CL = scls[slot];

            if (lane == 0) {
                float* o = out + ((size_t)b * MAXDET + d) * 6;
                o[0] = scx[slot]; o[1] = scy[slot];
                o[2] = swd[slot]; o[3] = sht[slot];
                o[4] = (float)CL; o[5] = __uint_as_float(mhi);
            }
            // branchless suppress (winner clears via kk==selKey)
#pragma unroll
            for (int t = 0; t < PER_LANE; t++) {
                float iw = fminf(rx2[t], X2) - fmaxf(rx1[t], X1);
                float ih = fminf(ry2[t], Y2) - fmaxf(ry1[t], Y1);
                float inter = fmaxf(iw, 0.f) * fmaxf(ih, 0.f);
                float iou = inter / (rar[t] + AR - inter + 1e-8f);
                bool kill = (kk[t] == selKey) ||
                            ((rcl[t] == CL) && (iou > IOU_T));
                kk[t] = kill ? 0ull : kk[t];
            }
        }
    }
    __syncthreads();

    // ---------------- exact full-array fallback (normally unreachable) ----
    if (sFallback) {
        float* sc = g_scores + (size_t)b * A;
        const float4* bx = g_boxes8 + (size_t)b * A * 2;
        for (int d = 0; d < MAXDET; d++) {
            u64 mk = 0;
            for (int i = tid; i < A; i += NMS_NT) {
                u64 k = ((u64)__float_as_uint(sc[i]) << 32) |
                        (unsigned)(0x7FFFFFFF - i);
                if (k > mk) mk = k;
            }
#pragma unroll
            for (int off = 16; off; off >>= 1) {
                u64 ok = __shfl_down_sync(0xffffffffu, mk, off);
                if (ok > mk) mk = ok;
            }
            if ((tid & 31) == 0) redk[tid >> 5] = mk;
            __syncthreads();
            if (tid < 32) {
                u64 k2 = (tid < NMS_NT / 32) ? redk[tid] : 0ull;
#pragma unroll
                for (int off = 16; off; off >>= 1) {
                    u64 ok = __shfl_down_sync(0xffffffffu, k2, off);
                    if (ok > k2) k2 = ok;
                }
                if (tid == 0) sBest = k2;
            }
            __syncthreads();
            u64 selKey = sBest;
            int   a = 0x7FFFFFFF - (int)(selKey & 0xFFFFFFFFull);
            float selScore = __uint_as_float((unsigned)(selKey >> 32));
            float4 p0 = bx[(size_t)a * 2 + 0];
            float4 p1 = bx[(size_t)a * 2 + 1];
            float X1 = p0.x - 0.5f * p0.z, Y1 = p0.y - 0.5f * p0.w;
            float X2 = p0.x + 0.5f * p0.z, Y2 = p0.y + 0.5f * p0.w;
            float AR = p0.z * p0.w;
            int   CL = (int)p1.x;
            if (tid == 0) {
                float* o = out + ((size_t)b * MAXDET + d) * 6;
                o[0] = p0.x; o[1] = p0.y; o[2] = p0.z;
                o[3] = p0.w; o[4] = p1.x; o[5] = selScore;
            }
            __syncthreads();
            for (int i = tid; i < A; i += NMS_NT) {
                if (i == a) { sc[i] = 0.0f; continue; }
                if (sc[i] == 0.0f) continue;
                float4 q0 = bx[(size_t)i * 2 + 0];
                float4 q1 = bx[(size_t)i * 2 + 1];
                if ((int)q1.x == CL) {
                    float iw = fminf(q0.x + 0.5f * q0.z, X2) - fmaxf(q0.x - 0.5f * q0.z, X1);
                    float ih = fminf(q0.y + 0.5f * q0.w, Y2) - fmaxf(q0.y - 0.5f * q0.w, Y1);
                    if (iw > 0.0f && ih > 0.0f) {
                        float inter = iw * ih;
                        float iou = inter / (q0.z * q0.w + AR - inter + 1e-8f);
                        if (iou > IOU_T) sc[i] = 0.0f;
                    }
                }
            }
            __syncthreads();
        }
    }
}

// ---------------- launch ----------------
extern "C" void kernel_launch(void* const* d_in, const int* in_sizes, int n_in,
                              void* d_out, int out_size) {
    const float *pred, *anch;
    int s0 = in_sizes[0], s1 = in_sizes[1];
    if (s0 >= s1) {
        pred = (const float*)d_in[0]; anch = (const float*)d_in[1];
    } else {
        pred = (const float*)d_in[1]; anch = (const float*)d_in[0];
        int t = s0; s0 = s1; s1 = t;
    }
    int A = s1 / 4;
    int B = out_size / (MAXDET * 6);
    int total = B * A;

    decode_kernel<<<(total + 255) / 256, 256>>>(pred, anch, B, A);
    thresh_kernel<<<B, 512>>>();
    compact_kernel<<<dim3(64, B), 256>>>(A);
    nms_kernel<<<B, NMS_NT>>>((float*)d_out, A);
}

// round 10
// speedup vs baseline: 3.1037x; 3.1037x over previous
#include <cuda_runtime.h>

#define DPRED    84
#define NCLS     80
#define MAXB     8
#define MAXA     76725
#define NBINS    4096
#define KMAX     512
#define NW       (KMAX / 32)
#define KTARGET  128
#define MAXDET   100
#define CONF_T   0.05f
#define IOU_T    0.5f
#define NMS_NT   256

typedef unsigned long long u64;
typedef unsigned int       u32;

// dynamic smem layout (bytes)
#define SM_SK    0
#define SM_MAT   (SM_SK  + KMAX * 8)
#define SM_X1    (SM_MAT + KMAX * NW * 4)
#define SM_Y1    (SM_X1  + KMAX * 4)
#define SM_X2    (SM_Y1  + KMAX * 4)
#define SM_Y2    (SM_X2  + KMAX * 4)
#define SM_AR    (SM_Y2  + KMAX * 4)
#define SM_CL    (SM_AR  + KMAX * 4)
#define SM_FLAG  (SM_CL  + KMAX * 4)
#define SM_DEAD  (SM_FLAG + NW * 4)
#define SM_ALIVE (SM_DEAD + NW * 4)
#define NMS_SMEM (SM_ALIVE + KMAX * 2)

// ---------------- device scratch (no allocation allowed) ----------------
__device__ float4 g_boxes8[MAXB * MAXA * 2];  // cx,cy,w,h | cls,conf,0,0
__device__ float  g_scores[MAXB * MAXA];      // conf if >= CONF_T else 0
__device__ int    g_hist[MAXB * NBINS];       // zero-init; re-zeroed by thresh
__device__ float  g_thresh[MAXB];
__device__ int    g_cnt[MAXB];
__device__ int    g_cand[MAXB * KMAX];

// ---------------- decode: thread per anchor (best measured config) -------
__global__ void __launch_bounds__(256)
decode_kernel(const float* __restrict__ pred,
              const float* __restrict__ anchors,
              int B, int A) {
    int i = blockIdx.x * blockDim.x + threadIdx.x;
    if (i >= B * A) return;

    const float4* row = reinterpret_cast<const float4*>(pred + (size_t)i * DPRED);
    float4 v0 = __ldg(row + 0);

    float best = -3.4e38f;
    int   cls  = 0;
#pragma unroll
    for (int j = 1; j <= 20; j++) {
        float4 c = __ldg(row + j);
        int base = (j - 1) * 4;
        if (c.x > best) { best = c.x; cls = base + 0; }
        if (c.y > best) { best = c.y; cls = base + 1; }
        if (c.z > best) { best = c.z; cls = base + 2; }
        if (c.w > best) { best = c.w; cls = base + 3; }
    }

    int b = i / A;
    int a = i - b * A;

    float4 an = __ldg(reinterpret_cast<const float4*>(anchors) + a);
    float cx = v0.x * 0.1f * an.z + an.x;
    float cy = v0.y * 0.1f * an.w + an.y;
    float w  = expf(v0.z * 0.2f) * an.z;
    float h  = expf(v0.w * 0.2f) * an.w;
    float conf = 1.0f / (1.0f + expf(-best));

    g_boxes8[(size_t)i * 2 + 0] = make_float4(cx, cy, w, h);
    g_boxes8[(size_t)i * 2 + 1] = make_float4((float)cls, conf, 0.f, 0.f);

    float s = (conf >= CONF_T) ? conf : 0.0f;
    g_scores[i] = s;
    if (s > 0.0f) {
        int bin = (int)(s * (float)NBINS);
        if (bin > NBINS - 1) bin = NBINS - 1;
        if (bin < 1) bin = 1;
        atomicAdd(&g_hist[b * NBINS + bin], 1);
    }
}

// ------- threshold from histogram (and re-zero hist for next call) -------
__global__ void __launch_bounds__(512)
thresh_kernel() {
    int b   = blockIdx.x;
    int tid = threadIdx.x;
    __shared__ int sh[NBINS];
    __shared__ int csum[128];

    for (int i = tid; i < NBINS; i += 512)
        sh[i] = g_hist[b * NBINS + i];
    __syncthreads();
    for (int i = tid; i < NBINS; i += 512)
        g_hist[b * NBINS + i] = 0;

    if (tid < 128) {
        int s = 0, base = tid * 32;
#pragma unroll
        for (int j = 0; j < 32; j++) s += sh[base + j];
        csum[tid] = s;
    }
    __syncthreads();

    if (tid == 0) {
        int cum = 0, binSel = NBINS, c = 128;
        while (c > 1 && cum < KTARGET && cum + csum[c - 1] <= KMAX) {
            c--; cum += csum[c]; binSel = c * 32;
        }
        if (cum < KTARGET && c >= 1) {
            for (int bin = c * 32 - 1; bin >= (c - 1) * 32 && bin >= 1; --bin) {
                int h = sh[bin];
                if (cum + h > KMAX) break;
                cum += h; binSel = bin;
                if (cum >= KTARGET) break;
            }
        }
        g_thresh[b] = (float)binSel / (float)NBINS;
        g_cnt[b]    = 0;
    }
}

// ---------------- compact candidates ----------------
__global__ void compact_kernel(int A) {
    int b = blockIdx.y;
    float th = g_thresh[b];
    const float* sc = g_scores + (size_t)b * A;
    for (int i = blockIdx.x * blockDim.x + threadIdx.x; i < A;
         i += gridDim.x * blockDim.x) {
        if (sc[i] > th) {
            int p = atomicAdd(&g_cnt[b], 1);
            if (p < KMAX) g_cand[b * KMAX + p] = i;
        }
    }
}

// ---- NMS: sort + all-pairs suppression matrix + bitmask resolve ---------
__global__ void __launch_bounds__(NMS_NT, 1)
nms_kernel(float* __restrict__ out, int A) {
    extern __shared__ char dynsm[];
    u64*   sk     = (u64*)  (dynsm + SM_SK);
    u32*   mat    = (u32*)  (dynsm + SM_MAT);
    float* sx1    = (float*)(dynsm + SM_X1);
    float* sy1    = (float*)(dynsm + SM_Y1);
    float* sx2    = (float*)(dynsm + SM_X2);
    float* sy2    = (float*)(dynsm + SM_Y2);
    float* sar    = (float*)(dynsm + SM_AR);
    float* scl    = (float*)(dynsm + SM_CL);
    u32*   flagm  = (u32*)  (dynsm + SM_FLAG);
    u32*   sdead  = (u32*)  (dynsm + SM_DEAD);
    unsigned short* aliveL = (unsigned short*)(dynsm + SM_ALIVE);

    __shared__ int sFallback, sAlive;
    __shared__ u64 sBest;
    __shared__ u64 redk[NMS_NT / 32];

    int b   = blockIdx.x;
    int tid = threadIdx.x;

    int cnt = g_cnt[b];
    bool overflow = (cnt > KMAX);
    if (cnt > KMAX) cnt = KMAX;

    // keys (conf in hi bits, 0x7FFFFFFF - anchor in lo); pad with 0
    for (int i = tid; i < KMAX; i += NMS_NT) {
        u64 k = 0;
        if (i < cnt) {
            int a = g_cand[b * KMAX + i];
            float4 p1 = g_boxes8[((size_t)b * A + a) * 2 + 1];
            k = ((u64)__float_as_uint(p1.y) << 32) | (u32)(0x7FFFFFFF - a);
        }
        sk[i] = k;
    }
    // zero matrix / masks
    for (int t = tid; t < KMAX * NW; t += NMS_NT) mat[t] = 0;
    if (tid < NW) { flagm[tid] = 0; sdead[tid] = 0; }
    if (tid == 0) { sFallback = overflow ? 1 : 0; sAlive = 0; }
    __syncthreads();

    // ---- bitonic sort, descending ----
    for (int k2 = 2; k2 <= KMAX; k2 <<= 1) {
        for (int j2 = k2 >> 1; j2 > 0; j2 >>= 1) {
            for (int i = tid; i < KMAX; i += NMS_NT) {
                int p = i ^ j2;
                if (p > i) {
                    u64 a = sk[i], c = sk[p];
                    bool descBlk = ((i & k2) == 0);
                    bool sw = descBlk ? (a < c) : (a > c);
                    if (sw) { sk[i] = c; sk[p] = a; }
                }
            }
            __syncthreads();
        }
    }

    // ---- gather box data for sorted slots ----
    for (int s = tid; s < KMAX; s += NMS_NT) {
        u64 key = sk[s];
        if (key != 0) {
            int a = 0x7FFFFFFF - (int)(key & 0xFFFFFFFFull);
            size_t base = ((size_t)b * A + a) * 2;
            float4 p0 = g_boxes8[base + 0];
            float4 p1 = g_boxes8[base + 1];
            float hw = 0.5f * p0.z, hh = 0.5f * p0.w;
            sx1[s] = p0.x - hw; sy1[s] = p0.y - hh;
            sx2[s] = p0.x + hw; sy2[s] = p0.y + hh;
            sar[s] = p0.z * p0.w;
            scl[s] = p1.x;
        } else {
            scl[s] = -1.0f;
        }
    }
    __syncthreads();

    // ---- suppression matrix: row i = set of j>i it suppresses ----
    // mirror pairing balances triangular work: rows tid and KMAX-1-tid
#pragma unroll
    for (int half = 0; half < 2; half++) {
        int i = half ? (KMAX - 1 - tid) : tid;
        if (i >= cnt || (half && i == tid)) continue;
        float ci = scl[i];
        float X1 = sx1[i], Y1 = sy1[i], X2 = sx2[i], Y2 = sy2[i];
        float AR = sar[i];
        u32 bits = 0; u32 rowany = 0;
        int wcur = (i + 1) >> 5;
        for (int j = i + 1; j < cnt; j++) {
            int w = j >> 5;
            if (w != wcur) {
                if (bits) { mat[i * NW + wcur] = bits; rowany = 1; }
                bits = 0; wcur = w;
            }
            if (scl[j] == ci) {
                float iw = fminf(sx2[j], X2) - fmaxf(sx1[j], X1);
                float ih = fminf(sy2[j], Y2) - fmaxf(sy1[j], Y1);
                if (iw > 0.0f && ih > 0.0f) {
                    float inter = iw * ih;
                    float iou = inter / (sar[j] + AR - inter + 1e-8f);
                    if (iou > IOU_T) bits |= 1u << (j & 31);
                }
            }
        }
        if (bits) { mat[i * NW + wcur] = bits; rowany = 1; }
        if (rowany) atomicOr(&flagm[i >> 5], 1u << (i & 31));
    }
    __syncthreads();

    // ---- resolve: greedy scan over sorted order via bitmasks ----
    if (tid == 0 && !sFallback) {
        int aliveCnt = 0;
#pragma unroll
        for (int w = 0; w < NW; w++) {
            int lo = w * 32;
            int nvalid = cnt - lo;
            if (nvalid <= 0) break;
            u32 validm = (nvalid >= 32) ? 0xFFFFFFFFu
                                        : ((1u << nvalid) - 1u);
            u32 candm = validm & ~sdead[w];
            u32 fl = flagm[w];
            while (candm) {
                int bb = __ffs(candm) - 1;
                candm &= candm - 1;
                aliveL[aliveCnt++] = (unsigned short)(lo + bb);
                if (fl & (1u << bb)) {          // rare: row suppresses others
                    int i = lo + bb;
#pragma unroll
                    for (int ww = 0; ww < NW; ww++)
                        sdead[ww] |= mat[i * NW + ww];
                    candm &= ~sdead[w];
                }
            }
        }
        sAlive = aliveCnt;
        if (aliveCnt < MAXDET) sFallback = 1;   // pool exhausted -> exact
    }
    __syncthreads();

    // ---- output: first MAXDET alive in sorted order ----
    if (!sFallback) {
        if (tid < MAXDET) {
            int s = aliveL[tid];
            u64 key = sk[s];
            int a = 0x7FFFFFFF - (int)(key & 0xFFFFFFFFull);
            size_t base = ((size_t)b * A + a) * 2;
            float4 p0 = g_boxes8[base + 0];
            float4 p1 = g_boxes8[base + 1];
            float* o = out + ((size_t)b * MAXDET + tid) * 6;
            o[0] = p0.x; o[1] = p0.y; o[2] = p0.z; o[3] = p0.w;
            o[4] = p1.x; o[5] = __uint_as_float((u32)(key >> 32));
        }
        return;
    }

    // ---------------- exact full-array fallback (normally unreachable) ----
    {
        float* sc = g_scores + (size_t)b * A;
        const float4* bx = g_boxes8 + (size_t)b * A * 2;
        for (int d = 0; d < MAXDET; d++) {
            u64 mk = 0;
            for (int i = tid; i < A; i += NMS_NT) {
                u64 k = ((u64)__float_as_uint(sc[i]) << 32) |
                        (u32)(0x7FFFFFFF - i);
                if (k > mk) mk = k;
            }
#pragma unroll
            for (int off = 16; off; off >>= 1) {
                u64 ok = __shfl_down_sync(0xffffffffu, mk, off);
                if (ok > mk) mk = ok;
            }
            if ((tid & 31) == 0) redk[tid >> 5] = mk;
            __syncthreads();
            if (tid < 32) {
                u64 k2 = (tid < NMS_NT / 32) ? redk[tid] : 0ull;
#pragma unroll
                for (int off = 16; off; off >>= 1) {
                    u64 ok = __shfl_down_sync(0xffffffffu, k2, off);
                    if (ok > k2) k2 = ok;
                }
                if (tid == 0) sBest = k2;
            }
            __syncthreads();
            u64 selKey = sBest;
            int   a = 0x7FFFFFFF - (int)(selKey & 0xFFFFFFFFull);
            float selScore = __uint_as_float((u32)(selKey >> 32));
            float4 p0 = bx[(size_t)a * 2 + 0];
            float4 p1 = bx[(size_t)a * 2 + 1];
            float X1 = p0.x - 0.5f * p0.z, Y1 = p0.y - 0.5f * p0.w;
            float X2 = p0.x + 0.5f * p0.z, Y2 = p0.y + 0.5f * p0.w;
            float AR = p0.z * p0.w;
            int   CL = (int)p1.x;
            if (tid == 0) {
                float* o = out + ((size_t)b * MAXDET + d) * 6;
                o[0] = p0.x; o[1] = p0.y; o[2] = p0.z;
                o[3] = p0.w; o[4] = p1.x; o[5] = selScore;
            }
            __syncthreads();
            for (int i = tid; i < A; i += NMS_NT) {
                if (i == a) { sc[i] = 0.0f; continue; }
                if (sc[i] == 0.0f) continue;
                float4 q0 = bx[(size_t)i * 2 + 0];
                float4 q1 = bx[(size_t)i * 2 + 1];
                if ((int)q1.x == CL) {
                    float iw = fminf(q0.x + 0.5f * q0.z, X2) - fmaxf(q0.x - 0.5f * q0.z, X1);
                    float ih = fminf(q0.y + 0.5f * q0.w, Y2) - fmaxf(q0.y - 0.5f * q0.w, Y1);
                    if (iw > 0.0f && ih > 0.0f) {
                        float inter = iw * ih;
                        float iou = inter / (q0.z * q0.w + AR - inter + 1e-8f);
                        if (iou > IOU_T) sc[i] = 0.0f;
                    }
                }
            }
            __syncthreads();
        }
    }
}

// ---------------- launch ----------------
extern "C" void kernel_launch(void* const* d_in, const int* in_sizes, int n_in,
                              void* d_out, int out_size) {
    const float *pred, *anch;
    int s0 = in_sizes[0], s1 = in_sizes[1];
    if (s0 >= s1) {
        pred = (const float*)d_in[0]; anch = (const float*)d_in[1];
    } else {
        pred = (const float*)d_in[1]; anch = (const float*)d_in[0];
        int t = s0; s0 = s1; s1 = t;
    }
    int A = s1 / 4;
    int B = out_size / (MAXDET * 6);
    int total = B * A;

    decode_kernel<<<(total + 255) / 256, 256>>>(pred, anch, B, A);
    thresh_kernel<<<B, 512>>>();
    compact_kernel<<<dim3(64, B), 256>>>(A);

    static int smem_set = 0;
    if (!smem_set) {
        cudaFuncSetAttribute(nms_kernel,
                             cudaFuncAttributeMaxDynamicSharedMemorySize, NMS_SMEM);
        smem_set = 1;
    }
    nms_kernel<<<B, NMS_NT, NMS_SMEM>>>((float*)d_out, A);
}